// round 4
// baseline (speedup 1.0000x reference)
#include <cuda_runtime.h>
#include <cuda_bf16.h>

// RNN: out[n,t,:] = tanh(x[n,t,:]@Wx + b + h_{t-1}@Wh), h_{-1}=h0.
// N=64, T=512, D=256, H=256, all fp32.
//
// Kernel 1: xW = x@Wx + b -> g_xw (SIMT f32x2 GEMM).
// Kernel 2: recurrence, 64 clusters x 2 CTAs. CTA r produces h columns
//   [r*128,+128). Each of 256 threads owns ONE output column j=t and holds
//   Wh[k_local][j] (128 weights) in registers, where k_local = the 128 rows
//   matching the CTA's own columns. Per step every thread computes the
//   partial over the LOCAL h half only; threads owning peer columns ship
//   {partial, step_tag} as one 8B st.shared::cluster.v2 into the peer's
//   inbox; threads owning local columns spin on their own inbox slot's tag,
//   then combine + tanh. No mbarrier, no bulk copy, no proxy fences.

#define ULL unsigned long long

static __device__ __forceinline__ ULL pk2(float lo, float hi) {
    ULL r; asm("mov.b64 %0, {%1,%2};" : "=l"(r) : "f"(lo), "f"(hi)); return r;
}
static __device__ __forceinline__ void upk2(ULL v, float& lo, float& hi) {
    asm("mov.b64 {%0,%1}, %2;" : "=f"(lo), "=f"(hi) : "l"(v));
}
static __device__ __forceinline__ ULL f2fma(ULL a, ULL b, ULL c) {
    ULL d; asm("fma.rn.f32x2 %0, %1, %2, %3;" : "=l"(d) : "l"(a), "l"(b), "l"(c)); return d;
}
static __device__ __forceinline__ ULL f2add(ULL a, ULL b) {
    ULL d; asm("add.rn.f32x2 %0, %1, %2;" : "=l"(d) : "l"(a), "l"(b)); return d;
}
static __device__ __forceinline__ unsigned int smem_u32(const void* p) {
    unsigned int a;
    asm("{ .reg .u64 t; cvta.to.shared.u64 t, %1; cvt.u32.u64 %0, t; }"
        : "=r"(a) : "l"(p));
    return a;
}
static __device__ __forceinline__ float fast_tanh(float x) {
    float e = __expf(x + x);
    return 1.0f - __fdividef(2.0f, e + 1.0f);
}

// Scratch for the input projection (no cudaMalloc allowed).
__device__ float g_xw[64 * 512 * 256];

// ---------------------------------------------------------------------------
// Kernel 1: xW GEMM.  C[M=32768, H=256] = X[M,256] * Wx[256,256] + b
// ---------------------------------------------------------------------------
__global__ void __launch_bounds__(256) gemm_xw(const float* __restrict__ X,
                                               const float* __restrict__ Wx,
                                               const float* __restrict__ bias) {
    __shared__ __align__(16) float As[16][128];  // [k][m]
    __shared__ __align__(16) float Bs[16][128];  // [k][h]

    const int t    = threadIdx.x;
    const int m0   = blockIdx.x * 128;
    const int h0   = blockIdx.y * 128;
    const int warp = t >> 5;
    const int lane = t & 31;

    ULL acc[8][4];
#pragma unroll
    for (int p = 0; p < 8; p++)
#pragma unroll
        for (int c = 0; c < 4; c++) acc[p][c] = 0ULL;

    for (int k0 = 0; k0 < 256; k0 += 16) {
#pragma unroll
        for (int i = 0; i < 2; i++) {
            int s   = t * 2 + i;
            int row = s >> 2;
            int kq  = s & 3;
            float4 v = *(const float4*)&X[(size_t)(m0 + row) * 256 + k0 + kq * 4];
            As[kq * 4 + 0][row] = v.x;
            As[kq * 4 + 1][row] = v.y;
            As[kq * 4 + 2][row] = v.z;
            As[kq * 4 + 3][row] = v.w;
        }
#pragma unroll
        for (int i = 0; i < 2; i++) {
            int s  = t * 2 + i;
            int kr = s >> 5;
            int hq = s & 31;
            float4 v = *(const float4*)&Wx[(size_t)(k0 + kr) * 256 + h0 + hq * 4];
            *(float4*)&Bs[kr][hq * 4] = v;
        }
        __syncthreads();

#pragma unroll
        for (int kk = 0; kk < 16; kk++) {
            const ulonglong2* ar = (const ulonglong2*)&As[kk][warp * 16];
            ulonglong2 q0 = ar[0], q1 = ar[1], q2 = ar[2], q3 = ar[3];
            ULL ap[8] = {q0.x, q0.y, q1.x, q1.y, q2.x, q2.y, q3.x, q3.y};
            float4 bv = *(const float4*)&Bs[kk][lane * 4];
            ULL bs0 = pk2(bv.x, bv.x), bs1 = pk2(bv.y, bv.y);
            ULL bs2 = pk2(bv.z, bv.z), bs3 = pk2(bv.w, bv.w);
#pragma unroll
            for (int p = 0; p < 8; p++) {
                acc[p][0] = f2fma(ap[p], bs0, acc[p][0]);
                acc[p][1] = f2fma(ap[p], bs1, acc[p][1]);
                acc[p][2] = f2fma(ap[p], bs2, acc[p][2]);
                acc[p][3] = f2fma(ap[p], bs3, acc[p][3]);
            }
        }
        __syncthreads();
    }

    float4 bb = *(const float4*)&bias[h0 + lane * 4];
#pragma unroll
    for (int p = 0; p < 8; p++) {
        float lo0, hi0, lo1, hi1, lo2, hi2, lo3, hi3;
        upk2(acc[p][0], lo0, hi0);
        upk2(acc[p][1], lo1, hi1);
        upk2(acc[p][2], lo2, hi2);
        upk2(acc[p][3], lo3, hi3);
        int m = m0 + warp * 16 + p * 2;
        float4 r0 = make_float4(lo0 + bb.x, lo1 + bb.y, lo2 + bb.z, lo3 + bb.w);
        float4 r1 = make_float4(hi0 + bb.x, hi1 + bb.y, hi2 + bb.z, hi3 + bb.w);
        *(float4*)&g_xw[(size_t)m * 256 + h0 + lane * 4]       = r0;
        *(float4*)&g_xw[(size_t)(m + 1) * 256 + h0 + lane * 4] = r1;
    }
}

// ---------------------------------------------------------------------------
// Kernel 2: recurrence. grid = 128 blocks, cluster (2,1,1).
// ---------------------------------------------------------------------------
__global__ void __launch_bounds__(256, 1) __cluster_dims__(2, 1, 1)
rnn_scan(const float* __restrict__ h0g, const float* __restrict__ Wh,
         float* __restrict__ out) {
    // Local h half (the columns THIS CTA produces), double-buffered by parity.
    __shared__ __align__(16) float h_buf[2][128];
    // Inbox: peer-sent {partial, tag} per local column, double-buffered.
    __shared__ __align__(16) float2 inbox[2][128];

    const int t     = threadIdx.x;       // owned output column j = t
    const int n     = blockIdx.x >> 1;
    const int r     = blockIdx.x & 1;
    const int jbase = r * 128;
    const bool mine = ((t >> 7) == r);   // column t is produced by this CTA
    const int jloc  = t & 127;           // index within the owning CTA's half

    // Register-resident weights: Wh[k][t] for the CTA's local k rows
    // (k in [r*128, r*128+128)), packed in k-pairs.
    ULL W2[64];
#pragma unroll
    for (int k2 = 0; k2 < 64; k2++) {
        float w0 = Wh[(size_t)(jbase + 2 * k2) * 256 + t];
        float w1 = Wh[(size_t)(jbase + 2 * k2 + 1) * 256 + t];
        W2[k2] = pk2(w0, w1);
    }

    // Init: local h half from h0; inbox tags poisoned.
    if (t < 128) {
        h_buf[0][t] = h0g[(size_t)n * 256 + jbase + t];
        inbox[0][t] = make_float2(0.f, __int_as_float(-1));
        inbox[1][t] = make_float2(0.f, __int_as_float(-1));
    }
    // Cluster barrier: inbox init + h_buf[0] done before any peer traffic.
    asm volatile("barrier.cluster.arrive.aligned;" ::: "memory");
    asm volatile("barrier.cluster.wait.aligned;" ::: "memory");

    const unsigned int peer = r ^ 1;
    // Threads owning PEER columns: remote address of peer's inbox slot.
    unsigned int rem_slot[2] = {0, 0};
    if (!mine) {
        unsigned int l0 = smem_u32(&inbox[0][jloc]);
        unsigned int l1 = smem_u32(&inbox[1][jloc]);
        asm("mapa.shared::cluster.u32 %0, %1, %2;" : "=r"(rem_slot[0]) : "r"(l0), "r"(peer));
        asm("mapa.shared::cluster.u32 %0, %1, %2;" : "=r"(rem_slot[1]) : "r"(l1), "r"(peer));
    }
    const unsigned int my_slot[2] = { smem_u32(&inbox[0][jloc]),
                                      smem_u32(&inbox[1][jloc]) };

    const float* xwp = g_xw + (size_t)n * 512 * 256 + jbase;
    float xw_cur = mine ? xwp[jloc] : 0.f;

    for (int s = 0; s < 512; s++) {
        const int cur = s & 1;
        const int nxt = cur ^ 1;

        // Partial over the LOCAL k half: 32x LDS.128 (broadcast), 4 chains.
        const ulonglong2* hp = (const ulonglong2*)&h_buf[cur][0];
        ULL a0 = 0ULL, a1 = 0ULL, a2 = 0ULL, a3 = 0ULL;
#pragma unroll
        for (int q = 0; q < 32; q += 2) {
            ulonglong2 v0 = hp[q];
            ulonglong2 v1 = hp[q + 1];
            a0 = f2fma(v0.x, W2[2 * q],     a0);
            a1 = f2fma(v0.y, W2[2 * q + 1], a1);
            a2 = f2fma(v1.x, W2[2 * q + 2], a2);
            a3 = f2fma(v1.y, W2[2 * q + 3], a3);
        }
        ULL ss = f2add(f2add(a0, a1), f2add(a2, a3));
        float plo, phi;
        upk2(ss, plo, phi);
        float part = plo + phi;

        if (!mine) {
            // Ship {partial, tag=s} to the owning CTA in ONE 8B store.
            asm volatile("st.shared::cluster.v2.f32 [%0], {%1, %2};"
                         :: "r"(rem_slot[cur]), "f"(part), "f"(__int_as_float(s))
                         : "memory");
        } else {
            // Prefetch next step's xw while the peer's partial is in flight.
            int sn = (s + 1 < 512) ? (s + 1) : s;
            float xw_nxt = xwp[(size_t)sn * 256 + jloc];

            // Spin on our inbox slot until this step's tag lands.
            float pin, ptag;
            do {
                asm volatile("ld.volatile.shared.v2.f32 {%0, %1}, [%2];"
                             : "=f"(pin), "=f"(ptag) : "r"(my_slot[cur]) : "memory");
            } while (__float_as_int(ptag) != s);

            float pre = xw_cur + part + pin;
            float hn  = fast_tanh(pre);
            h_buf[nxt][jloc] = hn;
            out[((size_t)n * 512 + s) * 256 + jbase + jloc] = hn;
            xw_cur = xw_nxt;
        }
        // h_buf[nxt] writes visible to all readers of the next iteration.
        __syncthreads();
    }

    // Don't exit while the peer may still write into our SMEM.
    asm volatile("barrier.cluster.arrive.aligned;" ::: "memory");
    asm volatile("barrier.cluster.wait.aligned;" ::: "memory");
}

// ---------------------------------------------------------------------------
extern "C" void kernel_launch(void* const* d_in, const int* in_sizes, int n_in,
                              void* d_out, int out_size) {
    const float* x  = (const float*)d_in[0];  // (64,512,256)
    const float* h0 = (const float*)d_in[1];  // (64,256)
    const float* Wx = (const float*)d_in[2];  // (256,256)
    const float* Wh = (const float*)d_in[3];  // (256,256)
    const float* b  = (const float*)d_in[4];  // (256,)
    float* out = (float*)d_out;               // (64,512,256)

    dim3 g1(256, 2);
    gemm_xw<<<g1, 256>>>(x, Wx, b);
    rnn_scan<<<128, 256>>>(h0, Wh, out);
    (void)in_sizes; (void)n_in; (void)out_size;
}

// round 5
// speedup vs baseline: 1.0306x; 1.0306x over previous
#include <cuda_runtime.h>
#include <cuda_bf16.h>

// RNN: out[n,t,:] = tanh(x[n,t,:]@Wx + b + h_{t-1}@Wh), h_{-1}=h0.
// N=64, T=512, D=256, H=256, all fp32.
//
// Kernel 1: xW = x@Wx + b -> g_xw (SIMT f32x2 GEMM).
// Kernel 2: recurrence, 64 clusters x 2 CTAs, 512 threads each. CTA r owns
//   output columns [r*128,+128). Thread t serves column j=t&127 with
//   k-quarter kq=t>>7 (64 k's, 32 f32x2 weight regs). Per step: 4 partials
//   per column -> smem reduce -> warps 0-3 combine + tanh -> one 512B
//   cp.async.bulk.shared::cluster ships the new h half to the peer with
//   mbarrier::complete_tx (R3's exchange, measured best).

#define ULL unsigned long long

static __device__ __forceinline__ ULL pk2(float lo, float hi) {
    ULL r; asm("mov.b64 %0, {%1,%2};" : "=l"(r) : "f"(lo), "f"(hi)); return r;
}
static __device__ __forceinline__ void upk2(ULL v, float& lo, float& hi) {
    asm("mov.b64 {%0,%1}, %2;" : "=f"(lo), "=f"(hi) : "l"(v));
}
static __device__ __forceinline__ ULL f2fma(ULL a, ULL b, ULL c) {
    ULL d; asm("fma.rn.f32x2 %0, %1, %2, %3;" : "=l"(d) : "l"(a), "l"(b), "l"(c)); return d;
}
static __device__ __forceinline__ ULL f2add(ULL a, ULL b) {
    ULL d; asm("add.rn.f32x2 %0, %1, %2;" : "=l"(d) : "l"(a), "l"(b)); return d;
}
static __device__ __forceinline__ unsigned int smem_u32(const void* p) {
    unsigned int a;
    asm("{ .reg .u64 t; cvta.to.shared.u64 t, %1; cvt.u32.u64 %0, t; }"
        : "=r"(a) : "l"(p));
    return a;
}
static __device__ __forceinline__ float fast_tanh(float x) {
    float e = __expf(x + x);
    return 1.0f - __fdividef(2.0f, e + 1.0f);
}
static __device__ __forceinline__ void wait_parity(unsigned int bar, unsigned int par) {
    unsigned int done;
    asm volatile(
        "{ .reg .pred p; "
        "mbarrier.try_wait.parity.acquire.cta.shared::cta.b64 p, [%1], %2; "
        "selp.b32 %0, 1, 0, p; }"
        : "=r"(done) : "r"(bar), "r"(par) : "memory");
    while (!done) {
        asm volatile(
            "{ .reg .pred p; "
            "mbarrier.try_wait.parity.acquire.cta.shared::cta.b64 p, [%1], %2, 0x989680; "
            "selp.b32 %0, 1, 0, p; }"
            : "=r"(done) : "r"(bar), "r"(par) : "memory");
    }
}

// Scratch for the input projection (no cudaMalloc allowed).
__device__ float g_xw[64 * 512 * 256];

// ---------------------------------------------------------------------------
// Kernel 1: xW GEMM.  C[M=32768, H=256] = X[M,256] * Wx[256,256] + b
// ---------------------------------------------------------------------------
__global__ void __launch_bounds__(256) gemm_xw(const float* __restrict__ X,
                                               const float* __restrict__ Wx,
                                               const float* __restrict__ bias) {
    __shared__ __align__(16) float As[16][128];  // [k][m]
    __shared__ __align__(16) float Bs[16][128];  // [k][h]

    const int t    = threadIdx.x;
    const int m0   = blockIdx.x * 128;
    const int h0   = blockIdx.y * 128;
    const int warp = t >> 5;
    const int lane = t & 31;

    ULL acc[8][4];
#pragma unroll
    for (int p = 0; p < 8; p++)
#pragma unroll
        for (int c = 0; c < 4; c++) acc[p][c] = 0ULL;

    for (int k0 = 0; k0 < 256; k0 += 16) {
#pragma unroll
        for (int i = 0; i < 2; i++) {
            int s   = t * 2 + i;
            int row = s >> 2;
            int kq  = s & 3;
            float4 v = *(const float4*)&X[(size_t)(m0 + row) * 256 + k0 + kq * 4];
            As[kq * 4 + 0][row] = v.x;
            As[kq * 4 + 1][row] = v.y;
            As[kq * 4 + 2][row] = v.z;
            As[kq * 4 + 3][row] = v.w;
        }
#pragma unroll
        for (int i = 0; i < 2; i++) {
            int s  = t * 2 + i;
            int kr = s >> 5;
            int hq = s & 31;
            float4 v = *(const float4*)&Wx[(size_t)(k0 + kr) * 256 + h0 + hq * 4];
            *(float4*)&Bs[kr][hq * 4] = v;
        }
        __syncthreads();

#pragma unroll
        for (int kk = 0; kk < 16; kk++) {
            const ulonglong2* ar = (const ulonglong2*)&As[kk][warp * 16];
            ulonglong2 q0 = ar[0], q1 = ar[1], q2 = ar[2], q3 = ar[3];
            ULL ap[8] = {q0.x, q0.y, q1.x, q1.y, q2.x, q2.y, q3.x, q3.y};
            float4 bv = *(const float4*)&Bs[kk][lane * 4];
            ULL bs0 = pk2(bv.x, bv.x), bs1 = pk2(bv.y, bv.y);
            ULL bs2 = pk2(bv.z, bv.z), bs3 = pk2(bv.w, bv.w);
#pragma unroll
            for (int p = 0; p < 8; p++) {
                acc[p][0] = f2fma(ap[p], bs0, acc[p][0]);
                acc[p][1] = f2fma(ap[p], bs1, acc[p][1]);
                acc[p][2] = f2fma(ap[p], bs2, acc[p][2]);
                acc[p][3] = f2fma(ap[p], bs3, acc[p][3]);
            }
        }
        __syncthreads();
    }

    float4 bb = *(const float4*)&bias[h0 + lane * 4];
#pragma unroll
    for (int p = 0; p < 8; p++) {
        float lo0, hi0, lo1, hi1, lo2, hi2, lo3, hi3;
        upk2(acc[p][0], lo0, hi0);
        upk2(acc[p][1], lo1, hi1);
        upk2(acc[p][2], lo2, hi2);
        upk2(acc[p][3], lo3, hi3);
        int m = m0 + warp * 16 + p * 2;
        float4 r0 = make_float4(lo0 + bb.x, lo1 + bb.y, lo2 + bb.z, lo3 + bb.w);
        float4 r1 = make_float4(hi0 + bb.x, hi1 + bb.y, hi2 + bb.z, hi3 + bb.w);
        *(float4*)&g_xw[(size_t)m * 256 + h0 + lane * 4]       = r0;
        *(float4*)&g_xw[(size_t)(m + 1) * 256 + h0 + lane * 4] = r1;
    }
}

// ---------------------------------------------------------------------------
// Kernel 2: recurrence. grid = 128 blocks x 512 thr, cluster (2,1,1).
// ---------------------------------------------------------------------------
__global__ void __launch_bounds__(512, 1) __cluster_dims__(2, 1, 1)
rnn_scan(const float* __restrict__ h0g, const float* __restrict__ Wh,
         float* __restrict__ out) {
    __shared__ __align__(16) float h_buf[2][256];   // full h, peer fills other half
    __shared__ float p_s[2][3][128];                // partials of kq=1..3, by parity
    __shared__ __align__(8) ULL mbar;

    const int t     = threadIdx.x;
    const int n     = blockIdx.x >> 1;
    const int r     = blockIdx.x & 1;
    const int jbase = r * 128;
    const int j     = t & 127;          // output column (within local half)
    const int kq    = t >> 7;           // k-quarter 0..3
    const bool comb = (kq == 0);        // warps 0-3 combine

    // Register-resident weights: Wh[kq*64 + k][jbase+j], k-pairs (32 regs ULL).
    ULL W2[32];
#pragma unroll
    for (int k2 = 0; k2 < 32; k2++) {
        float w0 = Wh[(size_t)(kq * 64 + 2 * k2) * 256 + jbase + j];
        float w1 = Wh[(size_t)(kq * 64 + 2 * k2 + 1) * 256 + jbase + j];
        W2[k2] = pk2(w0, w1);
    }

    if (t < 256) h_buf[0][t] = h0g[(size_t)n * 256 + t];

    const unsigned int bar_local = smem_u32(&mbar);
    if (t == 0) {
        asm volatile("mbarrier.init.shared.b64 [%0], %1;"
                     :: "r"(bar_local), "r"(1) : "memory");
    }
    asm volatile("barrier.cluster.arrive.aligned;" ::: "memory");
    asm volatile("barrier.cluster.wait.aligned;" ::: "memory");

    const unsigned int peer = r ^ 1;
    unsigned int rem_dst[2], rem_bar;
    {
        unsigned int l0 = smem_u32(&h_buf[0][jbase]);
        unsigned int l1 = smem_u32(&h_buf[1][jbase]);
        asm("mapa.shared::cluster.u32 %0, %1, %2;" : "=r"(rem_dst[0]) : "r"(l0), "r"(peer));
        asm("mapa.shared::cluster.u32 %0, %1, %2;" : "=r"(rem_dst[1]) : "r"(l1), "r"(peer));
        asm("mapa.shared::cluster.u32 %0, %1, %2;" : "=r"(rem_bar) : "r"(bar_local), "r"(peer));
    }
    const unsigned int src_loc[2] = { smem_u32(&h_buf[0][jbase]),
                                      smem_u32(&h_buf[1][jbase]) };
    const bool lead = (t == 0);

    const float* xwp = g_xw + (size_t)n * 512 * 256 + jbase;
    float xw_cur = comb ? xwp[j] : 0.f;

    for (int s = 0; s < 512; s++) {
        const int cur = s & 1;
        const int nxt = cur ^ 1;

        // Prefetch next step's input projection (combiners only).
        float xw_nxt = 0.f;
        if (comb) {
            int sn = (s + 1 < 512) ? (s + 1) : s;
            xw_nxt = xwp[(size_t)sn * 256 + j];
        }

        // Partial dot over this thread's 64 k's: 16x LDS.128 (broadcast),
        // 4 chains of 8 FFMA2.
        const ulonglong2* hp = (const ulonglong2*)&h_buf[cur][kq * 64];
        ULL a0 = 0ULL, a1 = 0ULL, a2 = 0ULL, a3 = 0ULL;
#pragma unroll
        for (int q = 0; q < 16; q += 2) {
            ulonglong2 v0 = hp[q];
            ulonglong2 v1 = hp[q + 1];
            a0 = f2fma(v0.x, W2[2 * q],     a0);
            a1 = f2fma(v0.y, W2[2 * q + 1], a1);
            a2 = f2fma(v1.x, W2[2 * q + 2], a2);
            a3 = f2fma(v1.y, W2[2 * q + 3], a3);
        }
        ULL ss = f2add(f2add(a0, a1), f2add(a2, a3));
        float plo, phi;
        upk2(ss, plo, phi);
        float part = plo + phi;

        if (!comb) p_s[cur][kq - 1][j] = part;   // publish k-quarter partial
        __syncthreads();                         // p_s visible; h_buf[cur] reads done

        if (comb) {
            float pre = xw_cur + part + p_s[cur][0][j]
                      + p_s[cur][1][j] + p_s[cur][2][j];
            float hn  = fast_tanh(pre);
            h_buf[nxt][jbase + j] = hn;                       // local half
            out[((size_t)n * 512 + s) * 256 + jbase + j] = hn;
            xw_cur = xw_nxt;
            // Combiner-group barrier: local half complete (writers==readers).
            asm volatile("bar.sync 1, 128;" ::: "memory");
            if (lead) {
                // Account for the peer's 512B landing in our h_buf[nxt].
                asm volatile("mbarrier.arrive.expect_tx.shared::cta.b64 _, [%0], %1;"
                             :: "r"(bar_local), "r"(512) : "memory");
                // Order generic smem writes before the async-proxy read.
                asm volatile("fence.proxy.async.shared::cta;" ::: "memory");
                // One bulk copy: our 512B half -> peer h_buf[nxt][jbase].
                asm volatile(
                    "cp.async.bulk.shared::cluster.shared::cta.mbarrier::complete_tx::bytes "
                    "[%0], [%1], %2, [%3];"
                    :: "r"(rem_dst[nxt]), "r"(src_loc[nxt]), "r"(512), "r"(rem_bar)
                    : "memory");
            }
        }

        // Everyone waits for the peer's half of h_buf[nxt] (acquire),
        // then a CTA barrier makes the local combiner writes visible too.
        wait_parity(bar_local, (unsigned)(s & 1));
        __syncthreads();
    }

    // Don't exit while the peer may still write into our SMEM.
    asm volatile("barrier.cluster.arrive.aligned;" ::: "memory");
    asm volatile("barrier.cluster.wait.aligned;" ::: "memory");
}

// ---------------------------------------------------------------------------
extern "C" void kernel_launch(void* const* d_in, const int* in_sizes, int n_in,
                              void* d_out, int out_size) {
    const float* x  = (const float*)d_in[0];  // (64,512,256)
    const float* h0 = (const float*)d_in[1];  // (64,256)
    const float* Wx = (const float*)d_in[2];  // (256,256)
    const float* Wh = (const float*)d_in[3];  // (256,256)
    const float* b  = (const float*)d_in[4];  // (256,)
    float* out = (float*)d_out;               // (64,512,256)

    dim3 g1(256, 2);
    gemm_xw<<<g1, 256>>>(x, Wx, b);
    rnn_scan<<<128, 512>>>(h0, Wh, out);
    (void)in_sizes; (void)n_in; (void)out_size;
}

// round 8
// speedup vs baseline: 1.4552x; 1.4121x over previous
#include <cuda_runtime.h>
#include <cuda_bf16.h>

// RNN: out[n,t,:] = tanh(x[n,t,:]@Wx + b + h_{t-1}@Wh), h_{-1}=h0.
// N=64, T=512, D=256, H=256, all fp32.
//
// Kernel 1: xW = x@Wx + b -> g_xw (SIMT f32x2 GEMM).
// Kernel 2: recurrence, 64 clusters x 2 CTAs, 256 threads. CTA r owns output
//   columns [r*128,+128). Warps 0-3 (group A) dot the LOCAL k-half and
//   publish p_s (never touch the mbarrier). Warps 4-7 (group B) wait for the
//   peer half, dot it, combine + tanh, write the new local half, and send it
//   to the peer via one 512B cp.async.bulk with mbarrier::complete_tx.
//   Producer/consumer named barriers (2: A->B p_s, 3: B->A hloc) keep both
//   groups off each other's critical path.

#define ULL unsigned long long

static __device__ __forceinline__ ULL pk2(float lo, float hi) {
    ULL r; asm("mov.b64 %0, {%1,%2};" : "=l"(r) : "f"(lo), "f"(hi)); return r;
}
static __device__ __forceinline__ void upk2(ULL v, float& lo, float& hi) {
    asm("mov.b64 {%0,%1}, %2;" : "=f"(lo), "=f"(hi) : "l"(v));
}
static __device__ __forceinline__ ULL f2fma(ULL a, ULL b, ULL c) {
    ULL d; asm("fma.rn.f32x2 %0, %1, %2, %3;" : "=l"(d) : "l"(a), "l"(b), "l"(c)); return d;
}
static __device__ __forceinline__ ULL f2add(ULL a, ULL b) {
    ULL d; asm("add.rn.f32x2 %0, %1, %2;" : "=l"(d) : "l"(a), "l"(b)); return d;
}
static __device__ __forceinline__ unsigned int smem_u32(const void* p) {
    unsigned int a;
    asm("{ .reg .u64 t; cvta.to.shared.u64 t, %1; cvt.u32.u64 %0, t; }"
        : "=r"(a) : "l"(p));
    return a;
}
static __device__ __forceinline__ float fast_tanh(float x) {
    float e = __expf(x + x);
    return 1.0f - __fdividef(2.0f, e + 1.0f);
}
static __device__ __forceinline__ void wait_parity(unsigned int bar, unsigned int par) {
    unsigned int done;
    asm volatile(
        "{ .reg .pred p; "
        "mbarrier.try_wait.parity.acquire.cta.shared::cta.b64 p, [%1], %2; "
        "selp.b32 %0, 1, 0, p; }"
        : "=r"(done) : "r"(bar), "r"(par) : "memory");
    while (!done) {
        asm volatile(
            "{ .reg .pred p; "
            "mbarrier.try_wait.parity.acquire.cta.shared::cta.b64 p, [%1], %2, 0x989680; "
            "selp.b32 %0, 1, 0, p; }"
            : "=r"(done) : "r"(bar), "r"(par) : "memory");
    }
}
// 128-element dot: 32x LDS.128, 64 FFMA2 over 8 accumulator chains.
static __device__ __forceinline__ float dot128(const ulonglong2* hp, const ULL* W2) {
    ULL a0 = 0ULL, a1 = 0ULL, a2 = 0ULL, a3 = 0ULL;
    ULL a4 = 0ULL, a5 = 0ULL, a6 = 0ULL, a7 = 0ULL;
#pragma unroll
    for (int q = 0; q < 32; q += 4) {
        ulonglong2 v0 = hp[q],     v1 = hp[q + 1];
        ulonglong2 v2 = hp[q + 2], v3 = hp[q + 3];
        a0 = f2fma(v0.x, W2[2 * q],     a0);
        a1 = f2fma(v0.y, W2[2 * q + 1], a1);
        a2 = f2fma(v1.x, W2[2 * q + 2], a2);
        a3 = f2fma(v1.y, W2[2 * q + 3], a3);
        a4 = f2fma(v2.x, W2[2 * q + 4], a4);
        a5 = f2fma(v2.y, W2[2 * q + 5], a5);
        a6 = f2fma(v3.x, W2[2 * q + 6], a6);
        a7 = f2fma(v3.y, W2[2 * q + 7], a7);
    }
    ULL ss = f2add(f2add(f2add(a0, a1), f2add(a2, a3)),
                   f2add(f2add(a4, a5), f2add(a6, a7)));
    float lo, hi;
    upk2(ss, lo, hi);
    return lo + hi;
}

// Scratch for the input projection (no cudaMalloc allowed).
__device__ float g_xw[64 * 512 * 256];

// ---------------------------------------------------------------------------
// Kernel 1: xW GEMM.  C[M=32768, H=256] = X[M,256] * Wx[256,256] + b
// ---------------------------------------------------------------------------
__global__ void __launch_bounds__(256) gemm_xw(const float* __restrict__ X,
                                               const float* __restrict__ Wx,
                                               const float* __restrict__ bias) {
    __shared__ __align__(16) float As[16][128];  // [k][m]
    __shared__ __align__(16) float Bs[16][128];  // [k][h]

    const int t    = threadIdx.x;
    const int m0   = blockIdx.x * 128;
    const int h0   = blockIdx.y * 128;
    const int warp = t >> 5;
    const int lane = t & 31;

    ULL acc[8][4];
#pragma unroll
    for (int p = 0; p < 8; p++)
#pragma unroll
        for (int c = 0; c < 4; c++) acc[p][c] = 0ULL;

    for (int k0 = 0; k0 < 256; k0 += 16) {
#pragma unroll
        for (int i = 0; i < 2; i++) {
            int s   = t * 2 + i;
            int row = s >> 2;
            int kq  = s & 3;
            float4 v = *(const float4*)&X[(size_t)(m0 + row) * 256 + k0 + kq * 4];
            As[kq * 4 + 0][row] = v.x;
            As[kq * 4 + 1][row] = v.y;
            As[kq * 4 + 2][row] = v.z;
            As[kq * 4 + 3][row] = v.w;
        }
#pragma unroll
        for (int i = 0; i < 2; i++) {
            int s  = t * 2 + i;
            int kr = s >> 5;
            int hq = s & 31;
            float4 v = *(const float4*)&Wx[(size_t)(k0 + kr) * 256 + h0 + hq * 4];
            *(float4*)&Bs[kr][hq * 4] = v;
        }
        __syncthreads();

#pragma unroll
        for (int kk = 0; kk < 16; kk++) {
            const ulonglong2* ar = (const ulonglong2*)&As[kk][warp * 16];
            ulonglong2 q0 = ar[0], q1 = ar[1], q2 = ar[2], q3 = ar[3];
            ULL ap[8] = {q0.x, q0.y, q1.x, q1.y, q2.x, q2.y, q3.x, q3.y};
            float4 bv = *(const float4*)&Bs[kk][lane * 4];
            ULL bs0 = pk2(bv.x, bv.x), bs1 = pk2(bv.y, bv.y);
            ULL bs2 = pk2(bv.z, bv.z), bs3 = pk2(bv.w, bv.w);
#pragma unroll
            for (int p = 0; p < 8; p++) {
                acc[p][0] = f2fma(ap[p], bs0, acc[p][0]);
                acc[p][1] = f2fma(ap[p], bs1, acc[p][1]);
                acc[p][2] = f2fma(ap[p], bs2, acc[p][2]);
                acc[p][3] = f2fma(ap[p], bs3, acc[p][3]);
            }
        }
        __syncthreads();
    }

    float4 bb = *(const float4*)&bias[h0 + lane * 4];
#pragma unroll
    for (int p = 0; p < 8; p++) {
        float lo0, hi0, lo1, hi1, lo2, hi2, lo3, hi3;
        upk2(acc[p][0], lo0, hi0);
        upk2(acc[p][1], lo1, hi1);
        upk2(acc[p][2], lo2, hi2);
        upk2(acc[p][3], lo3, hi3);
        int m = m0 + warp * 16 + p * 2;
        float4 r0 = make_float4(lo0 + bb.x, lo1 + bb.y, lo2 + bb.z, lo3 + bb.w);
        float4 r1 = make_float4(hi0 + bb.x, hi1 + bb.y, hi2 + bb.z, hi3 + bb.w);
        *(float4*)&g_xw[(size_t)m * 256 + h0 + lane * 4]       = r0;
        *(float4*)&g_xw[(size_t)(m + 1) * 256 + h0 + lane * 4] = r1;
    }
}

// ---------------------------------------------------------------------------
// Kernel 2: recurrence. grid = 128 blocks x 256 thr, cluster (2,1,1).
// ---------------------------------------------------------------------------
__global__ void __launch_bounds__(256, 1) __cluster_dims__(2, 1, 1)
rnn_scan(const float* __restrict__ h0g, const float* __restrict__ Wh,
         float* __restrict__ out) {
    __shared__ __align__(16) float hloc[2][128];   // our columns of h
    __shared__ __align__(16) float hrem[2][128];   // peer's columns (bulk-filled)
    __shared__ float p_s[2][128];                  // group A partials
    __shared__ __align__(8) ULL mbar;

    const int t     = threadIdx.x;
    const int n     = blockIdx.x >> 1;
    const int r     = blockIdx.x & 1;
    const int jbase = r * 128;
    const int j     = t & 127;
    const int g     = t >> 7;              // 0 = group A (local), 1 = group B
    // Group A dots k in [jbase, jbase+128) (locally produced h components);
    // group B dots k in [jbase^128, ...) (peer-produced) and combines.
    const int kbase = (g == 0) ? jbase : (jbase ^ 128);

    // Register-resident weight slice: Wh[kbase+k][jbase+j], k-pairs.
    ULL W2[64];
#pragma unroll
    for (int k2 = 0; k2 < 64; k2++) {
        float w0 = Wh[(size_t)(kbase + 2 * k2) * 256 + jbase + j];
        float w1 = Wh[(size_t)(kbase + 2 * k2 + 1) * 256 + jbase + j];
        W2[k2] = pk2(w0, w1);
    }

    if (g == 0) hloc[0][j] = h0g[(size_t)n * 256 + jbase + j];
    else        hrem[0][j] = h0g[(size_t)n * 256 + (jbase ^ 128) + j];

    const unsigned int bar_local = smem_u32(&mbar);
    if (t == 0) {
        asm volatile("mbarrier.init.shared.b64 [%0], %1;"
                     :: "r"(bar_local), "r"(1) : "memory");
    }
    // Cluster-wide barrier: init writes visible everywhere before traffic.
    asm volatile("barrier.cluster.arrive.aligned;" ::: "memory");
    asm volatile("barrier.cluster.wait.aligned;" ::: "memory");

    const unsigned int peer = r ^ 1;
    unsigned int rem_dst[2], rem_bar;
    {
        unsigned int l0 = smem_u32(&hrem[0][0]);
        unsigned int l1 = smem_u32(&hrem[1][0]);
        asm("mapa.shared::cluster.u32 %0, %1, %2;" : "=r"(rem_dst[0]) : "r"(l0), "r"(peer));
        asm("mapa.shared::cluster.u32 %0, %1, %2;" : "=r"(rem_dst[1]) : "r"(l1), "r"(peer));
        asm("mapa.shared::cluster.u32 %0, %1, %2;" : "=r"(rem_bar) : "r"(bar_local), "r"(peer));
    }
    const unsigned int src_loc[2] = { smem_u32(&hloc[0][0]), smem_u32(&hloc[1][0]) };

    const float* xwp = g_xw + (size_t)n * 512 * 256 + jbase;
    float xw_cur = (g == 1) ? xwp[j] : 0.f;

    if (g == 0) {
        // ----- Group A: local-half dotter, never waits on the mbarrier -----
        for (int s = 0; s < 512; s++) {
            const int cur = s & 1;
            if (s > 0) {
                // Wait for B's hloc[cur] writes from step s-1.
                asm volatile("bar.sync 3, 256;" ::: "memory");
            }
            float part = dot128((const ulonglong2*)&hloc[cur][0], W2);
            p_s[cur][j] = part;
            asm volatile("bar.arrive 2, 256;" ::: "memory");
        }
    } else {
        // ----- Group B: remote-half dotter + combiner + sender -----
        for (int s = 0; s < 512; s++) {
            const int cur = s & 1;
            const int nxt = cur ^ 1;

            // Prefetch next step's input projection.
            int sn = (s + 1 < 512) ? (s + 1) : s;
            float xw_nxt = xwp[(size_t)sn * 256 + j];

            // Wait for the peer's half of h[cur] (step s-1's send).
            if (s > 0) wait_parity(bar_local, (unsigned)((s & 1) ^ 1));

            float part = dot128((const ulonglong2*)&hrem[cur][0], W2);

            // A's p_s[cur] ready (A arrived long ago in steady state).
            asm volatile("bar.sync 2, 256;" ::: "memory");

            float pre = xw_cur + part + p_s[cur][j];
            float hn  = fast_tanh(pre);
            hloc[nxt][j] = hn;
            if (s < 511) {
                // Release A for step s+1 (non-blocking).
                asm volatile("bar.arrive 3, 256;" ::: "memory");
                // B-internal: all 128 hloc[nxt] slots written (bulk src ready).
                asm volatile("bar.sync 1, 128;" ::: "memory");
                if (t == 128) {
                    asm volatile("mbarrier.arrive.expect_tx.shared::cta.b64 _, [%0], %1;"
                                 :: "r"(bar_local), "r"(512) : "memory");
                    asm volatile("fence.proxy.async.shared::cta;" ::: "memory");
                    asm volatile(
                        "cp.async.bulk.shared::cluster.shared::cta.mbarrier::complete_tx::bytes "
                        "[%0], [%1], %2, [%3];"
                        :: "r"(rem_dst[nxt]), "r"(src_loc[nxt]), "r"(512), "r"(rem_bar)
                        : "memory");
                }
            }
            out[((size_t)n * 512 + s) * 256 + jbase + j] = hn;
            xw_cur = xw_nxt;
        }
    }

    // Don't exit while the peer may still write into our SMEM.
    asm volatile("barrier.cluster.arrive.aligned;" ::: "memory");
    asm volatile("barrier.cluster.wait.aligned;" ::: "memory");
}

// ---------------------------------------------------------------------------
extern "C" void kernel_launch(void* const* d_in, const int* in_sizes, int n_in,
                              void* d_out, int out_size) {
    const float* x  = (const float*)d_in[0];  // (64,512,256)
    const float* h0 = (const float*)d_in[1];  // (64,256)
    const float* Wx = (const float*)d_in[2];  // (256,256)
    const float* Wh = (const float*)d_in[3];  // (256,256)
    const float* b  = (const float*)d_in[4];  // (256,)
    float* out = (float*)d_out;               // (64,512,256)

    dim3 g1(256, 2);
    gemm_xw<<<g1, 256>>>(x, Wx, b);
    rnn_scan<<<128, 256>>>(h0, Wh, out);
    (void)in_sizes; (void)n_in; (void)out_size;
}